// round 3
// baseline (speedup 1.0000x reference)
#include <cuda_runtime.h>
#include <math.h>

// Problem constants (fixed shapes per reference)
#define NN    10000
#define INC   128
#define H1C   8
#define C1C   128
#define D1    1024      // H1C*C1C
#define OUTC  64
#define MAXE  200000
#define MAXEE (MAXE + NN)

// ---------------- device scratch (no allocations allowed) ----------------
__device__ int   g_src[MAXEE];
__device__ int   g_dst[MAXEE];
__device__ float g_h1[NN * D1];     // layer-1 features, later reused as elu output
__device__ float g_num1[NN * D1];
__device__ float g_den1[NN * H1C];
__device__ float g_as1[NN * H1C];
__device__ float g_ad1[NN * H1C];
__device__ float g_z[NN * OUTC];
__device__ float g_num2[NN * OUTC];
__device__ float g_den2[NN];
__device__ float g_as2[NN];
__device__ float g_ad2[NN];
__device__ int   g_is64;

// ---------------- dtype detection for edge_index ----------------
// If edge_index is int64 (values < 2^31), every odd 32-bit word is zero.
__global__ void k_detect(const int* __restrict__ ei, int E) {
    __shared__ int nz;
    if (threadIdx.x == 0) nz = 0;
    __syncthreads();
    int n = E < 1000 ? E : 1000;
    int local = 0;
    for (int i = threadIdx.x; i < n; i += blockDim.x)
        if (ei[2 * i + 1] != 0) local = 1;
    if (local) atomicOr(&nz, 1);
    __syncthreads();
    if (threadIdx.x == 0) g_is64 = (nz == 0) ? 1 : 0;
}

// Build int32 src/dst with self-loops appended.
__global__ void k_build_edges(const void* __restrict__ ei, int E, int total) {
    int i = blockIdx.x * blockDim.x + threadIdx.x;
    if (i >= total) return;
    if (i < E) {
        if (g_is64) {
            const long long* p = (const long long*)ei;
            g_src[i] = (int)p[i];
            g_dst[i] = (int)p[E + i];
        } else {
            const int* p = (const int*)ei;
            g_src[i] = p[i];
            g_dst[i] = p[E + i];
        }
    } else {
        int n = i - E;
        g_src[i] = n;
        g_dst[i] = n;
    }
}

// Zero all accumulators (grid-stride).
__global__ void k_zeroall() {
    int i = blockIdx.x * blockDim.x + threadIdx.x;
    int stride = gridDim.x * blockDim.x;
    for (int j = i; j < NN * D1; j += stride)  g_num1[j] = 0.f;
    for (int j = i; j < NN * H1C; j += stride) g_den1[j] = 0.f;
    for (int j = i; j < NN * OUTC; j += stride) g_num2[j] = 0.f;
    for (int j = i; j < NN; j += stride)        g_den2[j] = 0.f;
}

// ---------------- tiled fp32 SGEMM core (device function) ----------------
// C[M,N] = A[M,K] @ B[K,N]; 64x64 tile, BK=16, 256 threads, 4x4 per thread.
__device__ __forceinline__ void sgemm_body(const float* __restrict__ A,
                                           const float* __restrict__ B,
                                           float* __restrict__ C,
                                           int M, int N, int K) {
    __shared__ float As[16][65];
    __shared__ float Bs[16][65];
    int tid = threadIdx.x;
    int row0 = blockIdx.y * 64, col0 = blockIdx.x * 64;
    int tx = tid & 15, ty = tid >> 4;
    float acc[4][4] = {};
    for (int k0 = 0; k0 < K; k0 += 16) {
#pragma unroll
        for (int i = 0; i < 4; i++) {
            int idx = tid + i * 256;
            int m = idx >> 4, kk = idx & 15;
            int gm = row0 + m;
            As[kk][m] = (gm < M) ? A[(size_t)gm * K + k0 + kk] : 0.f;
            int n2 = idx & 63, k2 = idx >> 6;
            Bs[k2][n2] = B[(size_t)(k0 + k2) * N + col0 + n2];
        }
        __syncthreads();
#pragma unroll
        for (int kk = 0; kk < 16; kk++) {
            float a[4], b[4];
#pragma unroll
            for (int i = 0; i < 4; i++) a[i] = As[kk][ty * 4 + i];
#pragma unroll
            for (int j = 0; j < 4; j++) b[j] = Bs[kk][tx * 4 + j];
#pragma unroll
            for (int i = 0; i < 4; i++)
#pragma unroll
                for (int j = 0; j < 4; j++) acc[i][j] += a[i] * b[j];
        }
        __syncthreads();
    }
#pragma unroll
    for (int i = 0; i < 4; i++) {
        int gm = row0 + ty * 4 + i;
        if (gm < M) {
#pragma unroll
            for (int j = 0; j < 4; j++)
                C[(size_t)gm * N + col0 + tx * 4 + j] = acc[i][j];
        }
    }
}

// GEMM1: g_h1 = x @ W1   (globals referenced from device code only)
__global__ void k_gemm1(const float* __restrict__ x, const float* __restrict__ W1) {
    sgemm_body(x, W1, g_h1, NN, D1, INC);
}

// GEMM2: g_z = g_h1 @ W2
__global__ void k_gemm2(const float* __restrict__ W2) {
    sgemm_body(g_h1, W2, g_z, NN, OUTC, D1);
}

// ---------------- layer-1 attention coefficients: warp per (node, head) ----------------
__global__ void k_alpha1(const float* __restrict__ asrc, const float* __restrict__ adst) {
    int w = (blockIdx.x * blockDim.x + threadIdx.x) >> 5;
    int lane = threadIdx.x & 31;
    if (w >= NN * H1C) return;
    int n = w >> 3, hh = w & 7;
    const float* hp = g_h1 + (size_t)n * D1 + hh * C1C;
    const float* ap = asrc + hh * C1C;
    const float* bp = adst + hh * C1C;
    float s = 0.f, d = 0.f;
#pragma unroll
    for (int j = 0; j < 4; j++) {
        float v = hp[lane + j * 32];
        s += v * ap[lane + j * 32];
        d += v * bp[lane + j * 32];
    }
    for (int o = 16; o; o >>= 1) {
        s += __shfl_down_sync(0xffffffffu, s, o);
        d += __shfl_down_sync(0xffffffffu, d, o);
    }
    if (lane == 0) { g_as1[w] = s; g_ad1[w] = d; }
}

// ---------------- fused edge pass 1 (softmax numerator+denominator) ----------------
// One warp per edge; 8 heads x 128 channels. No max-subtraction needed (self-loops
// guarantee den >= exp(e_self); |e| is O(5) so exp never overflows).
__global__ void k_edge1(int EE) {
    int w = (blockIdx.x * blockDim.x + threadIdx.x) >> 5;
    int lane = threadIdx.x & 31;
    if (w >= EE) return;
    int s = g_src[w], d = g_dst[w];
    const float* hs = g_h1 + (size_t)s * D1;
    float* nd = g_num1 + (size_t)d * D1;
#pragma unroll
    for (int hh = 0; hh < H1C; hh++) {
        float e = g_as1[s * H1C + hh] + g_ad1[d * H1C + hh];
        e = e > 0.f ? e : 0.2f * e;
        float wgt = __expf(e);
        if (lane == 0) atomicAdd(&g_den1[d * H1C + hh], wgt);
#pragma unroll
        for (int j = 0; j < 4; j++) {
            int c = hh * C1C + j * 32 + lane;
            atomicAdd(&nd[c], wgt * hs[c]);
        }
    }
}

// out1 = elu(num1/den1 + b1), written back into g_h1 (layer-2 input)
__global__ void k_elu(const float* __restrict__ b1) {
    int i = blockIdx.x * blockDim.x + threadIdx.x;
    if (i >= NN * D1) return;
    int n = i >> 10, c = i & 1023, hh = c >> 7;
    float v = g_num1[i] / (g_den1[n * H1C + hh] + 1e-16f) + b1[c];
    g_h1[i] = v > 0.f ? v : expm1f(v);
}

// layer-2 attention coefficients: warp per node (64 channels)
__global__ void k_alpha2(const float* __restrict__ a2s, const float* __restrict__ a2d) {
    int w = (blockIdx.x * blockDim.x + threadIdx.x) >> 5;
    int lane = threadIdx.x & 31;
    if (w >= NN) return;
    const float* zp = g_z + (size_t)w * OUTC;
    float s = zp[lane] * a2s[lane] + zp[lane + 32] * a2s[lane + 32];
    float d = zp[lane] * a2d[lane] + zp[lane + 32] * a2d[lane + 32];
    for (int o = 16; o; o >>= 1) {
        s += __shfl_down_sync(0xffffffffu, s, o);
        d += __shfl_down_sync(0xffffffffu, d, o);
    }
    if (lane == 0) { g_as2[w] = s; g_ad2[w] = d; }
}

// fused edge pass 2: warp per edge, 64 channels
__global__ void k_edge2(int EE) {
    int w = (blockIdx.x * blockDim.x + threadIdx.x) >> 5;
    int lane = threadIdx.x & 31;
    if (w >= EE) return;
    int s = g_src[w], d = g_dst[w];
    float e = g_as2[s] + g_ad2[d];
    e = e > 0.f ? e : 0.2f * e;
    float wgt = __expf(e);
    if (lane == 0) atomicAdd(&g_den2[d], wgt);
    const float* zs = g_z + (size_t)s * OUTC;
    float* nd = g_num2 + (size_t)d * OUTC;
    atomicAdd(&nd[lane], wgt * zs[lane]);
    atomicAdd(&nd[lane + 32], wgt * zs[lane + 32]);
}

__global__ void k_final(float* __restrict__ out, const float* __restrict__ b2) {
    int i = blockIdx.x * blockDim.x + threadIdx.x;
    if (i >= NN * OUTC) return;
    int n = i >> 6, c = i & 63;
    out[i] = g_num2[i] / (g_den2[n] + 1e-16f) + b2[c];
}

// ---------------- host launcher ----------------
extern "C" void kernel_launch(void* const* d_in, const int* in_sizes, int n_in,
                              void* d_out, int out_size) {
    const float* x    = (const float*)d_in[0];
    const void*  ei   = d_in[1];
    const float* W1   = (const float*)d_in[2];
    const float* a_s1 = (const float*)d_in[3];
    const float* a_d1 = (const float*)d_in[4];
    const float* b1   = (const float*)d_in[5];
    const float* W2   = (const float*)d_in[6];
    const float* a_s2 = (const float*)d_in[7];
    const float* a_d2 = (const float*)d_in[8];
    const float* b2   = (const float*)d_in[9];
    float* out = (float*)d_out;

    int E = in_sizes[1] / 2;
    if (E > MAXE) E = MAXE;
    int EE = E + NN;

    // edge dtype detection + edge list build
    k_detect<<<1, 256>>>((const int*)ei, E);
    k_build_edges<<<(EE + 255) / 256, 256>>>(ei, E, EE);

    // zero accumulators
    k_zeroall<<<4096, 256>>>();

    // layer 1: h1 = x @ W1
    k_gemm1<<<dim3(D1 / 64, (NN + 63) / 64), 256>>>(x, W1);
    // attention coefficients
    k_alpha1<<<(NN * H1C * 32 + 255) / 256, 256>>>(a_s1, a_d1);
    // fused softmax-aggregate edge pass
    k_edge1<<<(EE * 32 + 255) / 256, 256>>>(EE);
    // elu(num/den + b1) -> g_h1
    k_elu<<<(NN * D1 + 255) / 256, 256>>>(b1);

    // layer 2: z = h2 @ W2
    k_gemm2<<<dim3(OUTC / 64, (NN + 63) / 64), 256>>>(W2);
    k_alpha2<<<(NN * 32 + 255) / 256, 256>>>(a_s2, a_d2);
    k_edge2<<<(EE * 32 + 255) / 256, 256>>>(EE);
    k_final<<<(NN * OUTC + 255) / 256, 256>>>(out, b2);
}

// round 5
// speedup vs baseline: 1.5854x; 1.5854x over previous
#include <cuda_runtime.h>
#include <math.h>

// Problem constants (fixed shapes per reference)
#define NN    10000
#define INC   128
#define H1C   8
#define C1C   128
#define D1    1024      // H1C*C1C
#define OUTC  64
#define MAXE  200000
#define MAXEE (MAXE + NN)

// ---------------- device scratch (no allocations allowed) ----------------
__device__ int   g_src[MAXEE];
__device__ int   g_dst[MAXEE];
__device__ int   g_esrc[MAXEE];     // CSR: src per dst-sorted edge
__device__ int   g_rowptr[NN + 1];
__device__ int   g_cursor[NN];
__device__ int   g_deg[NN];
__device__ float g_h1[NN * D1];     // gemm1 output
__device__ float g_act[NN * D1];    // layer-1 elu output (layer-2 input)
__device__ float g_as1[NN * H1C];
__device__ float g_ad1[NN * H1C];
__device__ float g_z[NN * OUTC];
__device__ float g_as2[NN];
__device__ float g_ad2[NN];
__device__ int   g_is64;

// ---------------- dtype detection for edge_index ----------------
// If edge_index is int64 (values < 2^31), every odd 32-bit word is zero.
__global__ void k_detect(const int* __restrict__ ei, int E) {
    __shared__ int nz;
    if (threadIdx.x == 0) nz = 0;
    __syncthreads();
    int n = E < 1000 ? E : 1000;
    int local = 0;
    for (int i = threadIdx.x; i < n; i += blockDim.x)
        if (ei[2 * i + 1] != 0) local = 1;
    if (local) atomicOr(&nz, 1);
    __syncthreads();
    if (threadIdx.x == 0) g_is64 = (nz == 0) ? 1 : 0;
}

__global__ void k_zerodeg() {
    int i = blockIdx.x * blockDim.x + threadIdx.x;
    if (i < NN) g_deg[i] = 0;
}

// Build int32 src/dst with self-loops appended.
__global__ void k_build_edges(const void* __restrict__ ei, int E, int total) {
    int i = blockIdx.x * blockDim.x + threadIdx.x;
    if (i >= total) return;
    if (i < E) {
        if (g_is64) {
            const long long* p = (const long long*)ei;
            g_src[i] = (int)p[i];
            g_dst[i] = (int)p[E + i];
        } else {
            const int* p = (const int*)ei;
            g_src[i] = p[i];
            g_dst[i] = p[E + i];
        }
    } else {
        int n = i - E;
        g_src[i] = n;
        g_dst[i] = n;
    }
}

__global__ void k_hist(int EE) {
    int i = blockIdx.x * blockDim.x + threadIdx.x;
    if (i < EE) atomicAdd(&g_deg[g_dst[i]], 1);
}

// Exclusive scan of g_deg -> g_rowptr (and init g_cursor). Single block.
__global__ void k_scan() {
    __shared__ int sums[256];
    const int CH = (NN + 255) / 256;   // 40
    int tid = threadIdx.x;
    int base = tid * CH;
    int s = 0;
    for (int j = 0; j < CH; j++) {
        int idx = base + j;
        if (idx < NN) s += g_deg[idx];
    }
    sums[tid] = s;
    __syncthreads();
    // Hillis-Steele inclusive scan
    for (int off = 1; off < 256; off <<= 1) {
        int v = (tid >= off) ? sums[tid - off] : 0;
        __syncthreads();
        sums[tid] += v;
        __syncthreads();
    }
    int run = (tid == 0) ? 0 : sums[tid - 1];
    for (int j = 0; j < CH; j++) {
        int idx = base + j;
        if (idx < NN) {
            g_rowptr[idx] = run;
            g_cursor[idx] = run;
            run += g_deg[idx];
        }
    }
    if (tid == 255) g_rowptr[NN] = run;
}

__global__ void k_scatter(int EE) {
    int i = blockIdx.x * blockDim.x + threadIdx.x;
    if (i >= EE) return;
    int p = atomicAdd(&g_cursor[g_dst[i]], 1);
    g_esrc[p] = g_src[i];
}

// ---------------- SGEMM: 128x64 tile, BK=16, 256 threads, 8x4/thread, float4 ----------------
__device__ __forceinline__ void sgemm_body(const float* __restrict__ A,
                                           const float* __restrict__ B,
                                           float* __restrict__ C,
                                           int M, int N, int K) {
    __shared__ float As[16][132];
    __shared__ float Bs[16][68];
    int tid = threadIdx.x;
    int row0 = blockIdx.y * 128, col0 = blockIdx.x * 64;
    int tx = tid & 15, ty = tid >> 4;
    float acc[8][4] = {};
    for (int k0 = 0; k0 < K; k0 += 16) {
        // load A tile: 128 rows x 16 k = 512 float4s, 2 per thread
#pragma unroll
        for (int i = 0; i < 2; i++) {
            int f4 = tid + i * 256;
            int m = f4 >> 2;
            int kq = (f4 & 3) * 4;
            int gm = row0 + m;
            float4 v = make_float4(0.f, 0.f, 0.f, 0.f);
            if (gm < M) v = *(const float4*)&A[(size_t)gm * K + k0 + kq];
            As[kq + 0][m] = v.x;
            As[kq + 1][m] = v.y;
            As[kq + 2][m] = v.z;
            As[kq + 3][m] = v.w;
        }
        // load B tile: 16 k x 64 n = 256 float4s, 1 per thread
        {
            int k2 = tid >> 4, nq = tid & 15;
            float4 v = *(const float4*)&B[(size_t)(k0 + k2) * N + col0 + nq * 4];
            *(float4*)&Bs[k2][nq * 4] = v;
        }
        __syncthreads();
#pragma unroll
        for (int kk = 0; kk < 16; kk++) {
            float4 a0 = *(float4*)&As[kk][ty * 8];
            float4 a1 = *(float4*)&As[kk][ty * 8 + 4];
            float4 b  = *(float4*)&Bs[kk][tx * 4];
            float av[8] = {a0.x, a0.y, a0.z, a0.w, a1.x, a1.y, a1.z, a1.w};
            float bv[4] = {b.x, b.y, b.z, b.w};
#pragma unroll
            for (int i = 0; i < 8; i++)
#pragma unroll
                for (int j = 0; j < 4; j++) acc[i][j] += av[i] * bv[j];
        }
        __syncthreads();
    }
#pragma unroll
    for (int i = 0; i < 8; i++) {
        int gm = row0 + ty * 8 + i;
        if (gm < M) {
            float4 v = make_float4(acc[i][0], acc[i][1], acc[i][2], acc[i][3]);
            *(float4*)&C[(size_t)gm * N + col0 + tx * 4] = v;
        }
    }
}

__global__ void k_gemm1(const float* __restrict__ x, const float* __restrict__ W1) {
    sgemm_body(x, W1, g_h1, NN, D1, INC);
}
__global__ void k_gemm2(const float* __restrict__ W2) {
    sgemm_body(g_act, W2, g_z, NN, OUTC, D1);
}

// ---------------- layer-1 attention coefficients: warp per (node, head) ----------------
__global__ void k_alpha1(const float* __restrict__ asrc, const float* __restrict__ adst) {
    int w = (blockIdx.x * blockDim.x + threadIdx.x) >> 5;
    int lane = threadIdx.x & 31;
    if (w >= NN * H1C) return;
    int n = w >> 3, hh = w & 7;
    const float* hp = g_h1 + (size_t)n * D1 + hh * C1C;
    const float* ap = asrc + hh * C1C;
    const float* bp = adst + hh * C1C;
    float s = 0.f, d = 0.f;
#pragma unroll
    for (int j = 0; j < 4; j++) {
        float v = hp[lane + j * 32];
        s += v * ap[lane + j * 32];
        d += v * bp[lane + j * 32];
    }
    for (int o = 16; o; o >>= 1) {
        s += __shfl_down_sync(0xffffffffu, s, o);
        d += __shfl_down_sync(0xffffffffu, d, o);
    }
    if (lane == 0) { g_as1[w] = s; g_ad1[w] = d; }
}

// ---------------- CSR edge pass 1: one block per dst node, fused softmax+agg+elu ----------------
// 128 threads: thread t owns head h=t>>4, channels h*128 + (t&15)*8 .. +8.
// No max-subtraction needed: self-loop guarantees den >= exp(e_self); |e| is O(5).
__global__ void k_edge1(const float* __restrict__ b1) {
    int n = blockIdx.x;
    int tid = threadIdx.x;
    int h = tid >> 4;
    int c0 = h * C1C + (tid & 15) * 8;
    float ad = g_ad1[n * H1C + h];
    float acc[8] = {};
    float den = 0.f;
    int e0 = g_rowptr[n], e1 = g_rowptr[n + 1];
    int srcLane = threadIdx.x & 16;   // lane 0 or 16 within warp owns the expf
    for (int e = e0; e < e1; e++) {
        int s = g_esrc[e];
        float w = 0.f;
        if ((tid & 15) == 0) {
            float ev = g_as1[s * H1C + h] + ad;
            ev = ev > 0.f ? ev : 0.2f * ev;
            w = __expf(ev);
        }
        w = __shfl_sync(0xffffffffu, w, srcLane, 32);
        den += w;
        const float4* hp = (const float4*)(g_h1 + (size_t)s * D1 + c0);
        float4 p = hp[0], q = hp[1];
        acc[0] += w * p.x; acc[1] += w * p.y; acc[2] += w * p.z; acc[3] += w * p.w;
        acc[4] += w * q.x; acc[5] += w * q.y; acc[6] += w * q.z; acc[7] += w * q.w;
    }
    float inv = 1.f / (den + 1e-16f);
    float* op = g_act + (size_t)n * D1 + c0;
    float4 r0, r1;
    float v;
    v = acc[0] * inv + b1[c0 + 0]; r0.x = v > 0.f ? v : expm1f(v);
    v = acc[1] * inv + b1[c0 + 1]; r0.y = v > 0.f ? v : expm1f(v);
    v = acc[2] * inv + b1[c0 + 2]; r0.z = v > 0.f ? v : expm1f(v);
    v = acc[3] * inv + b1[c0 + 3]; r0.w = v > 0.f ? v : expm1f(v);
    v = acc[4] * inv + b1[c0 + 4]; r1.x = v > 0.f ? v : expm1f(v);
    v = acc[5] * inv + b1[c0 + 5]; r1.y = v > 0.f ? v : expm1f(v);
    v = acc[6] * inv + b1[c0 + 6]; r1.z = v > 0.f ? v : expm1f(v);
    v = acc[7] * inv + b1[c0 + 7]; r1.w = v > 0.f ? v : expm1f(v);
    ((float4*)op)[0] = r0;
    ((float4*)op)[1] = r1;
}

// layer-2 attention coefficients: warp per node (64 channels)
__global__ void k_alpha2(const float* __restrict__ a2s, const float* __restrict__ a2d) {
    int w = (blockIdx.x * blockDim.x + threadIdx.x) >> 5;
    int lane = threadIdx.x & 31;
    if (w >= NN) return;
    const float* zp = g_z + (size_t)w * OUTC;
    float s = zp[lane] * a2s[lane] + zp[lane + 32] * a2s[lane + 32];
    float d = zp[lane] * a2d[lane] + zp[lane + 32] * a2d[lane + 32];
    for (int o = 16; o; o >>= 1) {
        s += __shfl_down_sync(0xffffffffu, s, o);
        d += __shfl_down_sync(0xffffffffu, d, o);
    }
    if (lane == 0) { g_as2[w] = s; g_ad2[w] = d; }
}

// ---------------- CSR edge pass 2: warp per dst node, fused final output ----------------
__global__ void k_edge2(float* __restrict__ out, const float* __restrict__ b2) {
    int n = (blockIdx.x * blockDim.x + threadIdx.x) >> 5;
    int lane = threadIdx.x & 31;
    if (n >= NN) return;
    float ad = g_ad2[n];
    float acc0 = 0.f, acc1 = 0.f, den = 0.f;
    int e0 = g_rowptr[n], e1 = g_rowptr[n + 1];
    for (int e = e0; e < e1; e++) {
        int s = g_esrc[e];
        float w = 0.f;
        if (lane == 0) {
            float ev = g_as2[s] + ad;
            ev = ev > 0.f ? ev : 0.2f * ev;
            w = __expf(ev);
        }
        w = __shfl_sync(0xffffffffu, w, 0, 32);
        den += w;
        const float* zs = g_z + (size_t)s * OUTC;
        acc0 += w * zs[lane];
        acc1 += w * zs[lane + 32];
    }
    float inv = 1.f / (den + 1e-16f);
    out[(size_t)n * OUTC + lane]      = acc0 * inv + b2[lane];
    out[(size_t)n * OUTC + lane + 32] = acc1 * inv + b2[lane + 32];
}

// ---------------- host launcher ----------------
extern "C" void kernel_launch(void* const* d_in, const int* in_sizes, int n_in,
                              void* d_out, int out_size) {
    const float* x    = (const float*)d_in[0];
    const void*  ei   = d_in[1];
    const float* W1   = (const float*)d_in[2];
    const float* a_s1 = (const float*)d_in[3];
    const float* a_d1 = (const float*)d_in[4];
    const float* b1   = (const float*)d_in[5];
    const float* W2   = (const float*)d_in[6];
    const float* a_s2 = (const float*)d_in[7];
    const float* a_d2 = (const float*)d_in[8];
    const float* b2   = (const float*)d_in[9];
    float* out = (float*)d_out;

    int E = in_sizes[1] / 2;
    if (E > MAXE) E = MAXE;
    int EE = E + NN;

    // edge dtype detection + CSR build
    k_detect<<<1, 256>>>((const int*)ei, E);
    k_zerodeg<<<(NN + 255) / 256, 256>>>();
    k_build_edges<<<(EE + 255) / 256, 256>>>(ei, E, EE);
    k_hist<<<(EE + 255) / 256, 256>>>(EE);
    k_scan<<<1, 256>>>();
    k_scatter<<<(EE + 255) / 256, 256>>>(EE);

    // layer 1
    k_gemm1<<<dim3(D1 / 64, (NN + 127) / 128), 256>>>(x, W1);
    k_alpha1<<<(NN * H1C * 32 + 255) / 256, 256>>>(a_s1, a_d1);
    k_edge1<<<NN, 128>>>(b1);

    // layer 2
    k_gemm2<<<dim3(OUTC / 64, (NN + 127) / 128), 256>>>(W2);
    k_alpha2<<<(NN * 32 + 255) / 256, 256>>>(a_s2, a_d2);
    k_edge2<<<(NN * 32 + 255) / 256, 256>>>(out, b2);
}